// round 8
// baseline (speedup 1.0000x reference)
#include <cuda_runtime.h>
#include <math.h>

typedef unsigned long long ull;

#define SEQ   2048
#define DM    1024
#define NH    16
#define DH    128
#define HD    2048   // NH*DH

// ---------------- scratch ----------------
__device__ float g_Q[NH * SEQ * DH];   // compacted masked rows, head-major
__device__ float g_K[NH * SEQ * DH];
__device__ float g_V[NH * SEQ * DH];
__device__ float g_xpart[8][DM];
__device__ float g_xmean[DM];
__device__ float g_vpart[4][HD];
__device__ float g_vmean[HD];
__device__ int   g_mask[SEQ];
__device__ int   g_midx[SEQ];
__device__ int   g_kbest[NH * SEQ];
__device__ int   g_mcount;
__device__ int   g_mcount64;

// ---------------- f32x2 helpers ----------------
__device__ __forceinline__ void fma2(ull& d, ull a, ull b) {
    asm("fma.rn.f32x2 %0, %1, %2, %0;" : "+l"(d) : "l"(a), "l"(b));
}
__device__ __forceinline__ ull packf2(float lo, float hi) {
    ull r; asm("mov.b64 %0, {%1, %2};" : "=l"(r) : "f"(lo), "f"(hi)); return r;
}
__device__ __forceinline__ ull add2(ull a, ull b) {
    ull r; asm("add.rn.f32x2 %0, %1, %2;" : "=l"(r) : "l"(a), "l"(b)); return r;
}
__device__ __forceinline__ float f2sum(ull v) {
    float lo, hi; asm("mov.b64 {%0, %1}, %2;" : "=f"(lo), "=f"(hi) : "l"(v));
    return lo + hi;
}

// ---------------- mask decode + compaction ----------------
__global__ void mask_setup_kernel(const unsigned char* __restrict__ p)
{
    __shared__ int sm[SEQ];
    __shared__ int cnt[64];
    __shared__ int base[65];
    __shared__ int not_i32, not_f32;
    int t = threadIdx.x;               // 1024 threads
    if (t == 0) { not_i32 = 0; not_f32 = 0; }
    __syncthreads();
    if (t < 512) {
        unsigned w = ((const unsigned*)p)[t];
        if (!(w == 0u || w == 1u))          atomicExch(&not_i32, 1);
        if (!(w == 0u || w == 0x3F800000u)) atomicExch(&not_f32, 1);
    }
    __syncthreads();
    int cls = (!not_i32) ? 0 : ((!not_f32) ? 1 : 2);
    for (int i = t; i < SEQ; i += 1024) {
        int v;
        if (cls == 0)      v = (((const int*)p)[i]   != 0);
        else if (cls == 1) v = (((const float*)p)[i] != 0.0f);
        else               v = (p[i] != 0);
        sm[i] = v; g_mask[i] = v;
    }
    __syncthreads();
    if (t < 64) {
        int c = 0;
        for (int i = 0; i < 32; i++) c += sm[t * 32 + i];
        cnt[t] = c;
    }
    __syncthreads();
    if (t == 0) {
        int acc = 0;
        for (int c = 0; c < 64; c++) { base[c] = acc; acc += cnt[c]; }
        base[64] = acc;
        g_mcount = acc;
        g_mcount64 = (acc + 63) & ~63;
    }
    __syncthreads();
    if (t < 64) {
        int pos = base[t];
        for (int i = 0; i < 32; i++)
            if (sm[t * 32 + i]) g_midx[pos++] = t * 32 + i;
    }
    __syncthreads();
    int mc = base[64];
    for (int i = t; i < SEQ; i += 1024)
        if (i >= mc) g_midx[i] = 0;
}

// ---------------- proj tile device fn: 128(m) x 128(n), k-step 32, 8x4 micro ----------------
// dsm layout (ull): Xd[128][33] @0 (4224), Wp[32][65] @4224 (2080), ridx @6304 (128 int)
#define PROJ_SMEM_BYTES (6304 * 8 + 512)

__device__ __forceinline__ void proj_tile128(
    const float* __restrict__ X, const float* __restrict__ W,
    const float* __restrict__ bias, float* __restrict__ out,
    int m0, int n0, ull* dsm)
{
    ull* Xd   = dsm;            // [128][33]
    ull* Wp   = dsm + 4224;     // [32][65]
    int* ridx = (int*)(dsm + 6304);

    const int t  = threadIdx.x;
    const int tx = t & 15, ty = t >> 4;
    if (t < 128) ridx[t] = g_midx[m0 + t];
    __syncthreads();

    ull acc[8][4];
    #pragma unroll
    for (int i = 0; i < 8; i++)
        #pragma unroll
        for (int j = 0; j < 4; j++) acc[i][j] = 0ull;

    const int r0 = ty << 3;

    for (int k0 = 0; k0 < DM; k0 += 32) {
        // X tile: 128 rows x 32 k, duplicated pairs
        #pragma unroll
        for (int u = 0; u < 16; u++) {
            int i = t + u * 256;           // 0..4095
            int r = i >> 5, kk = i & 31;
            float x = X[(size_t)ridx[r] * DM + k0 + kk];
            Xd[r * 33 + kk] = packf2(x, x);
        }
        // W tile: 32 k-rows x 64 col-pairs (natural float2)
        #pragma unroll
        for (int u = 0; u < 8; u++) {
            int i = t + u * 256;           // 0..2047
            int kk = i >> 6, cp = i & 63;
            Wp[kk * 65 + cp] = *(const ull*)(W + (size_t)(k0 + kk) * HD + n0 + 2 * cp);
        }
        __syncthreads();
        #pragma unroll 2
        for (int kk = 0; kk < 32; kk++) {
            ull a[8];
            #pragma unroll
            for (int i = 0; i < 8; i++) a[i] = Xd[(r0 + i) * 33 + kk];
            const ull* wr = Wp + kk * 65 + tx;
            #pragma unroll
            for (int j = 0; j < 4; j++) {
                ull b = wr[16 * j];
                #pragma unroll
                for (int i = 0; i < 8; i++) fma2(acc[i][j], a[i], b);
            }
        }
        __syncthreads();
    }
    // n-tile is exactly one head slice (n0 128-aligned)
    const int h = n0 >> 7;
    #pragma unroll
    for (int j = 0; j < 4; j++) {
        int cp = tx + 16 * j;
        int d  = 2 * cp;
        ull bpair = *(const ull*)(bias + n0 + d);
        #pragma unroll
        for (int i = 0; i < 8; i++) {
            ull* dst = (ull*)(out + (size_t)(h * SEQ + m0 + r0 + i) * DH + d);
            *dst = add2(acc[i][j], bpair);
        }
    }
}

// ---------------- QK projection kernel ----------------
__global__ __launch_bounds__(256, 2) void projqk_kernel(
    const float* __restrict__ X,
    const float* __restrict__ Wq, const float* __restrict__ bq,
    const float* __restrict__ Wk, const float* __restrict__ bk)
{
    extern __shared__ __align__(16) ull dsm[];
    const int m0 = blockIdx.y << 7;
    if (m0 >= g_mcount64) return;
    const int n0 = blockIdx.x << 7;
    if (blockIdx.z == 0) proj_tile128(X, Wq, bq, g_Q, m0, n0, dsm);
    else                 proj_tile128(X, Wk, bk, g_K, m0, n0, dsm);
}

// ---------------- score tile (64q x 64k, f32x2) as device fn ----------------
// sm floats: Qs[64][130]@0 (8320), Ks@8320 (8320), rv@16640 (1024),
//            ri@17664 (1024), bestv@18688 (64), besti@18752 (64) -> 18816 floats
#define SC_FLOATS 18816

__device__ __forceinline__ void score_tile(int h, int q0, float* sm)
{
    float* Qs    = sm;
    float* Ks    = sm + 8320;
    float* rv    = sm + 16640;
    int*   ri    = (int*)(sm + 17664);
    float* bestv = sm + 18688;
    int*   besti = (int*)(sm + 18752);

    const int t  = threadIdx.x;
    const int tx = t & 15, ty = t >> 4;
    const int mc   = g_mcount;
    const int mc64 = g_mcount64;

    const float* Qg = g_Q + (size_t)(h * SEQ + q0) * DH;
    #pragma unroll
    for (int u = 0; u < 8; u++) {
        int i = t + u * 256;
        float4 v = ((const float4*)Qg)[i];
        int r = i >> 5, dd = (i & 31) << 2;
        ull* p = (ull*)&Qs[r * 130 + dd];
        p[0] = packf2(v.x, v.y); p[1] = packf2(v.z, v.w);
    }
    if (t < 64) { bestv[t] = INFINITY; besti[t] = 0; }

    const int r0 = ty << 2;
    const int nkt = mc64 >> 6;
    for (int kt = 0; kt < nkt; kt++) {
        const int k0 = kt << 6;
        __syncthreads();
        const float* Kg = g_K + (size_t)(h * SEQ + k0) * DH;
        #pragma unroll
        for (int u = 0; u < 8; u++) {
            int i = t + u * 256;
            float4 v = ((const float4*)Kg)[i];
            int r = i >> 5, dd = (i & 31) << 2;
            ull* p = (ull*)&Ks[r * 130 + dd];
            p[0] = packf2(v.x, v.y); p[1] = packf2(v.z, v.w);
        }
        __syncthreads();

        ull acc[4][4];
        #pragma unroll
        for (int i = 0; i < 4; i++)
            #pragma unroll
            for (int j = 0; j < 4; j++) acc[i][j] = 0ull;

        #pragma unroll 4
        for (int dp = 0; dp < 64; dp++) {
            ull a0 = *(const ull*)&Qs[(r0 + 0) * 130 + 2 * dp];
            ull a1 = *(const ull*)&Qs[(r0 + 1) * 130 + 2 * dp];
            ull a2 = *(const ull*)&Qs[(r0 + 2) * 130 + 2 * dp];
            ull a3 = *(const ull*)&Qs[(r0 + 3) * 130 + 2 * dp];
            #pragma unroll
            for (int j = 0; j < 4; j++) {
                ull b = *(const ull*)&Ks[(tx + 16 * j) * 130 + 2 * dp];
                fma2(acc[0][j], a0, b);
                fma2(acc[1][j], a1, b);
                fma2(acc[2][j], a2, b);
                fma2(acc[3][j], a3, b);
            }
        }

        #pragma unroll
        for (int i = 0; i < 4; i++) {
            int row = r0 + i;
            float bv_ = INFINITY; int bi = 0;
            #pragma unroll
            for (int j = 0; j < 4; j++) {
                int c = k0 + tx + 16 * j;
                float s = f2sum(acc[i][j]);
                s = (c < mc) ? s : INFINITY;
                if (s < bv_) { bv_ = s; bi = c; }
            }
            rv[row * 16 + tx] = bv_;
            ri[row * 16 + tx] = bi;
        }
        __syncthreads();
        if (t < 64) {
            float bv_ = bestv[t]; int bi = besti[t];
            #pragma unroll
            for (int p = 0; p < 16; p++) {
                float v = rv[t * 16 + p];
                if (v < bv_) { bv_ = v; bi = ri[t * 16 + p]; }
            }
            bestv[t] = bv_; besti[t] = bi;
        }
    }
    if (t < 64 && q0 + t < mc)
        g_kbest[h * SEQ + g_midx[q0 + t]] = besti[t];
}

// ---------------- vgemv block as device fn ----------------
__device__ __forceinline__ void vgemv_blk(int vid, const float* __restrict__ Wv, float* sm)
{
    // vid: 0..31 -> part = vid >> 3 (k-slice), cblk = vid & 7
    int part = vid >> 3, cblk = vid & 7;
    float* xm = sm;
    int t = threadIdx.x;
    xm[t] = g_xmean[part * 256 + t];
    __syncthreads();
    int c = cblk * 256 + t;
    float a0 = 0, a1 = 0, a2 = 0, a3 = 0;
    const float* Wp = Wv + (size_t)part * 256 * HD + c;
    for (int j = 0; j < 256; j += 4) {
        a0 += xm[j + 0] * Wp[(size_t)(j + 0) * HD];
        a1 += xm[j + 1] * Wp[(size_t)(j + 1) * HD];
        a2 += xm[j + 2] * Wp[(size_t)(j + 2) * HD];
        a3 += xm[j + 3] * Wp[(size_t)(j + 3) * HD];
    }
    g_vpart[part][c] = (a0 + a1) + (a2 + a3);
}

// ---------------- combined tail kernel: Vproj tiles + score tiles + vgemv ----------------
#define NBV 256   // (SEQ/128) * (HD/128) upper bound of V tiles
#define NBS 512   // NH * (SEQ/64) upper bound of score tiles
#define NBG 32    // vgemv blocks
#define TAIL_SMEM_BYTES (SC_FLOATS * 4 + 256)

__global__ __launch_bounds__(256, 2) void tail_kernel(
    const float* __restrict__ X,
    const float* __restrict__ Wv, const float* __restrict__ bv)
{
    extern __shared__ __align__(16) ull dsm[];
    const int bid = blockIdx.x;
    if (bid < NBV) {
        int mt = bid >> 4, nt = bid & 15;
        int m0 = mt << 7;
        if (m0 >= g_mcount64) return;
        proj_tile128(X, Wv, bv, g_V, m0, nt << 7, dsm);
    } else if (bid < NBV + NBS) {
        int sid = bid - NBV;
        int h = sid >> 5, qt = sid & 31;
        int q0 = qt << 6;
        if (q0 >= g_mcount) return;
        score_tile(h, q0, (float*)dsm);
    } else {
        vgemv_blk(bid - NBV - NBS, Wv, (float*)dsm);
    }
}

// ---------------- mean(X) ----------------
__global__ void xpart_kernel(const float* __restrict__ X)
{
    int j  = blockIdx.x * 256 + threadIdx.x;   // grid.x = 4
    int rb = blockIdx.y;                        // 8
    const float* p = X + (size_t)rb * 256 * DM + j;
    float s = 0.0f;
    #pragma unroll 8
    for (int r = 0; r < 256; r++) s += p[(size_t)r * DM];
    g_xpart[rb][j] = s;
}
__global__ void xmean_kernel(void)
{
    int j = blockIdx.x * 256 + threadIdx.x;    // grid 4
    float s = 0.0f;
    #pragma unroll
    for (int rb = 0; rb < 8; rb++) s += g_xpart[rb][j];
    g_xmean[j] = s * (1.0f / 2048.0f);
}
__global__ void vcombine_kernel(const float* __restrict__ bv)
{
    int c = blockIdx.x * 256 + threadIdx.x;    // grid 8
    g_vmean[c] = ((g_vpart[0][c] + g_vpart[1][c]) + (g_vpart[2][c] + g_vpart[3][c])) + bv[c];
}

// ---------------- output assembly ----------------
__global__ void assemble_kernel(float* __restrict__ out)
{
    int s = blockIdx.x;
    int t = threadIdx.x;               // 256
    if (g_mask[s]) {
        #pragma unroll
        for (int i = 0; i < 8; i++) {
            int idx = i * 256 + t;
            int h = idx >> 7, d = idx & 127;
            int kb = g_kbest[h * SEQ + s];
            out[(size_t)s * HD + idx] = g_V[(size_t)(h * SEQ + kb) * DH + d];
        }
    } else {
        #pragma unroll
        for (int i = 0; i < 8; i++) {
            int idx = i * 256 + t;
            out[(size_t)s * HD + idx] = g_vmean[idx];
        }
    }
}

// ---------------- launch ----------------
extern "C" void kernel_launch(void* const* d_in, const int* in_sizes, int n_in,
                              void* d_out, int out_size)
{
    const float* X          = (const float*)d_in[0];
    const unsigned char* mp = (const unsigned char*)d_in[1];
    const float* Wq = (const float*)d_in[2];
    const float* bq = (const float*)d_in[3];
    const float* Wk = (const float*)d_in[4];
    const float* bk = (const float*)d_in[5];
    const float* Wv = (const float*)d_in[6];
    const float* bv = (const float*)d_in[7];
    float* out = (float*)d_out;

    mask_setup_kernel<<<1, 1024>>>(mp);

    xpart_kernel<<<dim3(4, 8), 256>>>(X);
    xmean_kernel<<<4, 256>>>();

    cudaFuncSetAttribute(projqk_kernel, cudaFuncAttributeMaxDynamicSharedMemorySize, PROJ_SMEM_BYTES);
    projqk_kernel<<<dim3(HD / 128, SEQ / 128, 2), 256, PROJ_SMEM_BYTES>>>(X, Wq, bq, Wk, bk);

    cudaFuncSetAttribute(tail_kernel, cudaFuncAttributeMaxDynamicSharedMemorySize, TAIL_SMEM_BYTES);
    tail_kernel<<<NBV + NBS + NBG, 256, TAIL_SMEM_BYTES>>>(X, Wv, bv);

    vcombine_kernel<<<8, 256>>>(bv);

    assemble_kernel<<<SEQ, 256>>>(out);
}

// round 9
// speedup vs baseline: 1.0566x; 1.0566x over previous
#include <cuda_runtime.h>
#include <math.h>

typedef unsigned long long ull;

#define SEQ   2048
#define DM    1024
#define NH    16
#define DH    128
#define HD    2048   // NH*DH

// ---------------- scratch ----------------
__device__ float g_Q[NH * SEQ * DH];   // compacted masked rows, head-major
__device__ float g_K[NH * SEQ * DH];
__device__ float g_V[NH * SEQ * DH];
__device__ float g_xpart[8][DM];
__device__ float g_xmean[DM];
__device__ float g_vpart[4][HD];
__device__ float g_vmean[HD];
__device__ int   g_mask[SEQ];
__device__ int   g_midx[SEQ];
__device__ int   g_kbest[NH * SEQ];
__device__ int   g_mcount;
__device__ int   g_mcount64;
__device__ int   g_ticket;
__device__ int   g_qkdone;

// ---------------- f32x2 helpers ----------------
__device__ __forceinline__ void fma2(ull& d, ull a, ull b) {
    asm("fma.rn.f32x2 %0, %1, %2, %0;" : "+l"(d) : "l"(a), "l"(b));
}
__device__ __forceinline__ ull packf2(float lo, float hi) {
    ull r; asm("mov.b64 %0, {%1, %2};" : "=l"(r) : "f"(lo), "f"(hi)); return r;
}
__device__ __forceinline__ ull add2(ull a, ull b) {
    ull r; asm("add.rn.f32x2 %0, %1, %2;" : "=l"(r) : "l"(a), "l"(b)); return r;
}
__device__ __forceinline__ float f2sum(ull v) {
    float lo, hi; asm("mov.b64 {%0, %1}, %2;" : "=f"(lo), "=f"(hi) : "l"(v));
    return lo + hi;
}

// ---------------- mask decode + compaction (+ counter reset) ----------------
__global__ void mask_setup_kernel(const unsigned char* __restrict__ p)
{
    __shared__ int sm[SEQ];
    __shared__ int cnt[64];
    __shared__ int base[65];
    __shared__ int not_i32, not_f32;
    int t = threadIdx.x;               // 1024 threads
    if (t == 0) { not_i32 = 0; not_f32 = 0; g_ticket = 0; g_qkdone = 0; }
    __syncthreads();
    if (t < 512) {
        unsigned w = ((const unsigned*)p)[t];
        if (!(w == 0u || w == 1u))          atomicExch(&not_i32, 1);
        if (!(w == 0u || w == 0x3F800000u)) atomicExch(&not_f32, 1);
    }
    __syncthreads();
    int cls = (!not_i32) ? 0 : ((!not_f32) ? 1 : 2);
    for (int i = t; i < SEQ; i += 1024) {
        int v;
        if (cls == 0)      v = (((const int*)p)[i]   != 0);
        else if (cls == 1) v = (((const float*)p)[i] != 0.0f);
        else               v = (p[i] != 0);
        sm[i] = v; g_mask[i] = v;
    }
    __syncthreads();
    if (t < 64) {
        int c = 0;
        for (int i = 0; i < 32; i++) c += sm[t * 32 + i];
        cnt[t] = c;
    }
    __syncthreads();
    if (t == 0) {
        int acc = 0;
        for (int c = 0; c < 64; c++) { base[c] = acc; acc += cnt[c]; }
        base[64] = acc;
        g_mcount = acc;
        g_mcount64 = (acc + 63) & ~63;
    }
    __syncthreads();
    if (t < 64) {
        int pos = base[t];
        for (int i = 0; i < 32; i++)
            if (sm[t * 32 + i]) g_midx[pos++] = t * 32 + i;
    }
    __syncthreads();
    int mc = base[64];
    for (int i = t; i < SEQ; i += 1024)
        if (i >= mc) g_midx[i] = 0;
}

// ---------------- proj tile: 64(m) x 128(n), k-step 32, 4x4 micro (R7-proven) ----------------
// dsm (ull): Xd[64][33] @0 (2112), Wp[32][65] @2112 (2080), ridx @4192 (64 int)
__device__ __forceinline__ void proj_tile(
    const float* __restrict__ X, const float* __restrict__ W,
    const float* __restrict__ bias, float* __restrict__ out,
    int m0, int n0, ull* dsm)
{
    ull* Xd   = dsm;            // [64][33]
    ull* Wp   = dsm + 2112;     // [32][65]
    int* ridx = (int*)(dsm + 4192);

    const int t  = threadIdx.x;
    const int tx = t & 15, ty = t >> 4;
    if (t < 64) ridx[t] = g_midx[m0 + t];
    __syncthreads();

    ull acc[4][4];
    #pragma unroll
    for (int i = 0; i < 4; i++)
        #pragma unroll
        for (int j = 0; j < 4; j++) acc[i][j] = 0ull;

    const int r0 = ty << 2;

    for (int k0 = 0; k0 < DM; k0 += 32) {
        #pragma unroll
        for (int u = 0; u < 8; u++) {
            int i = t + u * 256;           // 0..2047
            int r = i >> 5, kk = i & 31;
            float x = X[(size_t)ridx[r] * DM + k0 + kk];
            Xd[r * 33 + kk] = packf2(x, x);
        }
        #pragma unroll
        for (int u = 0; u < 8; u++) {
            int i = t + u * 256;           // 0..2047
            int kk = i >> 6, cp = i & 63;
            Wp[kk * 65 + cp] = *(const ull*)(W + (size_t)(k0 + kk) * HD + n0 + 2 * cp);
        }
        __syncthreads();
        #pragma unroll 4
        for (int kk = 0; kk < 32; kk++) {
            ull a0 = Xd[(r0 + 0) * 33 + kk];
            ull a1 = Xd[(r0 + 1) * 33 + kk];
            ull a2 = Xd[(r0 + 2) * 33 + kk];
            ull a3 = Xd[(r0 + 3) * 33 + kk];
            const ull* wr = Wp + kk * 65 + tx;
            #pragma unroll
            for (int j = 0; j < 4; j++) {
                ull b = wr[16 * j];
                fma2(acc[0][j], a0, b);
                fma2(acc[1][j], a1, b);
                fma2(acc[2][j], a2, b);
                fma2(acc[3][j], a3, b);
            }
        }
        __syncthreads();
    }
    const int h = n0 >> 7;                 // n-tile spans exactly one head
    #pragma unroll
    for (int j = 0; j < 4; j++) {
        int cp = tx + 16 * j;
        int d  = 2 * cp;
        ull bpair = *(const ull*)(bias + n0 + d);
        #pragma unroll
        for (int i = 0; i < 4; i++) {
            ull* dst = (ull*)(out + (size_t)(h * SEQ + m0 + r0 + i) * DH + d);
            *dst = add2(acc[i][j], bpair);
        }
    }
}

// ---------------- score tile: 64q x 64k, register-resident argmin + shfl reduce ----------------
// sm floats: Qs[64][128] @0 (8192), Ks[64][130] @8192 (8320) -> 16512 floats
#define MEGA_SMEM_BYTES (16512 * 4)

__device__ __forceinline__ void score_tile(int h, int q0, float* sm)
{
    float* Qs = sm;            // stride 128 (a-loads are ty-broadcast: conflict-free)
    float* Ks = sm + 8192;     // stride 130 (b-loads conflict-free)

    const int t  = threadIdx.x;
    const int tx = t & 15, ty = t >> 4;
    const int mc = g_mcount;

    // load Q tile [64][128]
    const float* Qg = g_Q + (size_t)(h * SEQ + q0) * DH;
    #pragma unroll
    for (int u = 0; u < 8; u++) {
        int i = t + u * 256;
        float4 v = ((const float4*)Qg)[i];
        int r = i >> 5, dd = (i & 31) << 2;
        ull* p = (ull*)&Qs[r * 128 + dd];
        p[0] = packf2(v.x, v.y); p[1] = packf2(v.z, v.w);
    }

    float bv_[4]; int bi_[4];
    #pragma unroll
    for (int i = 0; i < 4; i++) { bv_[i] = INFINITY; bi_[i] = 0; }

    const int r0 = ty << 2;
    const int nkt = g_mcount64 >> 6;
    for (int kt = 0; kt < nkt; kt++) {
        const int k0 = kt << 6;
        __syncthreads();               // Q fill / prior reads done
        const float* Kg = g_K + (size_t)(h * SEQ + k0) * DH;
        #pragma unroll
        for (int u = 0; u < 8; u++) {
            int i = t + u * 256;
            float4 v = ((const float4*)Kg)[i];
            int r = i >> 5, dd = (i & 31) << 2;
            ull* p = (ull*)&Ks[r * 130 + dd];
            p[0] = packf2(v.x, v.y); p[1] = packf2(v.z, v.w);
        }
        __syncthreads();

        ull acc[4][4];
        #pragma unroll
        for (int i = 0; i < 4; i++)
            #pragma unroll
            for (int j = 0; j < 4; j++) acc[i][j] = 0ull;

        #pragma unroll 4
        for (int dp = 0; dp < 64; dp++) {
            ull a0 = *(const ull*)&Qs[(r0 + 0) * 128 + 2 * dp];
            ull a1 = *(const ull*)&Qs[(r0 + 1) * 128 + 2 * dp];
            ull a2 = *(const ull*)&Qs[(r0 + 2) * 128 + 2 * dp];
            ull a3 = *(const ull*)&Qs[(r0 + 3) * 128 + 2 * dp];
            #pragma unroll
            for (int j = 0; j < 4; j++) {
                ull b = *(const ull*)&Ks[(tx + 16 * j) * 130 + 2 * dp];
                fma2(acc[0][j], a0, b);
                fma2(acc[1][j], a1, b);
                fma2(acc[2][j], a2, b);
                fma2(acc[3][j], a3, b);
            }
        }
        #pragma unroll
        for (int i = 0; i < 4; i++) {
            #pragma unroll
            for (int j = 0; j < 4; j++) {
                int c = k0 + tx + 16 * j;
                float s = f2sum(acc[i][j]);
                if (c < mc && s < bv_[i]) { bv_[i] = s; bi_[i] = c; }
            }
        }
    }
    // half-warp shuffle argmin (row r0+i owned by 16 lanes with same ty)
    #pragma unroll
    for (int i = 0; i < 4; i++) {
        #pragma unroll
        for (int off = 8; off >= 1; off >>= 1) {
            float ov = __shfl_xor_sync(0xffffffffu, bv_[i], off);
            int   oi = __shfl_xor_sync(0xffffffffu, bi_[i], off);
            if (ov < bv_[i]) { bv_[i] = ov; bi_[i] = oi; }
        }
    }
    if (tx == 0) {
        #pragma unroll
        for (int i = 0; i < 4; i++) {
            int row = q0 + r0 + i;
            if (row < mc) g_kbest[h * SEQ + g_midx[row]] = bi_[i];
        }
    }
}

// ---------------- persistent mega kernel: QK proj -> (V proj | score) ----------------
__global__ __launch_bounds__(256, 3) void mega_kernel(
    const float* __restrict__ X,
    const float* __restrict__ Wq, const float* __restrict__ bq,
    const float* __restrict__ Wk, const float* __restrict__ bk,
    const float* __restrict__ Wv, const float* __restrict__ bv)
{
    extern __shared__ __align__(16) float sm[];
    __shared__ int s_id;
    const int nmt   = g_mcount64 >> 6;   // active m-tiles (64 rows each)
    const int nper  = nmt * 16;          // tiles per projection matrix
    const int nqk   = nper * 2;
    const int nv    = nper;
    const int nsc   = nper;              // 16 heads * nmt q-tiles
    const int total = nqk + nv + nsc;
    bool waited = false;

    for (;;) {
        __syncthreads();
        if (threadIdx.x == 0) s_id = atomicAdd(&g_ticket, 1);
        __syncthreads();
        const int id = s_id;
        if (id >= total) break;

        if (id < nqk) {
            int isK   = (id >= nper);
            int local = isK ? id - nper : id;
            int mt = local >> 4, nt = local & 15;
            proj_tile(X, isK ? Wk : Wq, isK ? bk : bq, isK ? g_K : g_Q,
                      mt << 6, nt << 7, (ull*)sm);
            __threadfence();
            __syncthreads();
            if (threadIdx.x == 0) atomicAdd(&g_qkdone, 1);
        } else if (id < nqk + nv) {
            int vid = id - nqk;
            int mt = vid >> 4, nt = vid & 15;
            proj_tile(X, Wv, bv, g_V, mt << 6, nt << 7, (ull*)sm);
        } else {
            int sid = id - nqk - nv;
            if (!waited) {
                if (threadIdx.x == 0) {
                    while (*(volatile int*)&g_qkdone < nqk) { }
                }
                __syncthreads();
                __threadfence();
                waited = true;
            }
            score_tile(sid & 15, (sid >> 4) << 6, sm);
        }
    }
}

// ---------------- mean(X) and mean-V via linearity ----------------
__global__ void xpart_kernel(const float* __restrict__ X)
{
    int j  = blockIdx.x * 256 + threadIdx.x;   // grid.x = 4
    int rb = blockIdx.y;                        // 8
    const float* p = X + (size_t)rb * 256 * DM + j;
    float s = 0.0f;
    #pragma unroll 8
    for (int r = 0; r < 256; r++) s += p[(size_t)r * DM];
    g_xpart[rb][j] = s;
}
__global__ void xmean_kernel(void)
{
    int j = blockIdx.x * 256 + threadIdx.x;    // grid 4
    float s = 0.0f;
    #pragma unroll
    for (int rb = 0; rb < 8; rb++) s += g_xpart[rb][j];
    g_xmean[j] = s * (1.0f / 2048.0f);
}
__global__ void vgemv_kernel(const float* __restrict__ Wv)
{
    __shared__ float xm[256];
    int t = threadIdx.x;
    int part = blockIdx.y;                     // 4 k-slices of 256
    xm[t] = g_xmean[part * 256 + t];
    __syncthreads();
    int c = blockIdx.x * 256 + t;              // grid.x 8
    float a0 = 0, a1 = 0, a2 = 0, a3 = 0;
    const float* Wp = Wv + (size_t)part * 256 * HD + c;
    for (int j = 0; j < 256; j += 4) {
        a0 += xm[j + 0] * Wp[(size_t)(j + 0) * HD];
        a1 += xm[j + 1] * Wp[(size_t)(j + 1) * HD];
        a2 += xm[j + 2] * Wp[(size_t)(j + 2) * HD];
        a3 += xm[j + 3] * Wp[(size_t)(j + 3) * HD];
    }
    g_vpart[part][c] = (a0 + a1) + (a2 + a3);
}
__global__ void vcombine_kernel(const float* __restrict__ bv)
{
    int c = blockIdx.x * 256 + threadIdx.x;    // grid 8
    g_vmean[c] = ((g_vpart[0][c] + g_vpart[1][c]) + (g_vpart[2][c] + g_vpart[3][c])) + bv[c];
}

// ---------------- output assembly ----------------
__global__ void assemble_kernel(float* __restrict__ out)
{
    int s = blockIdx.x;
    int t = threadIdx.x;               // 256
    if (g_mask[s]) {
        #pragma unroll
        for (int i = 0; i < 8; i++) {
            int idx = i * 256 + t;
            int h = idx >> 7, d = idx & 127;
            int kb = g_kbest[h * SEQ + s];
            out[(size_t)s * HD + idx] = g_V[(size_t)(h * SEQ + kb) * DH + d];
        }
    } else {
        #pragma unroll
        for (int i = 0; i < 8; i++) {
            int idx = i * 256 + t;
            out[(size_t)s * HD + idx] = g_vmean[idx];
        }
    }
}

// ---------------- launch ----------------
extern "C" void kernel_launch(void* const* d_in, const int* in_sizes, int n_in,
                              void* d_out, int out_size)
{
    const float* X          = (const float*)d_in[0];
    const unsigned char* mp = (const unsigned char*)d_in[1];
    const float* Wq = (const float*)d_in[2];
    const float* bq = (const float*)d_in[3];
    const float* Wk = (const float*)d_in[4];
    const float* bk = (const float*)d_in[5];
    const float* Wv = (const float*)d_in[6];
    const float* bv = (const float*)d_in[7];
    float* out = (float*)d_out;

    mask_setup_kernel<<<1, 1024>>>(mp);

    xpart_kernel<<<dim3(4, 8), 256>>>(X);
    xmean_kernel<<<4, 256>>>();

    cudaFuncSetAttribute(mega_kernel, cudaFuncAttributeMaxDynamicSharedMemorySize, MEGA_SMEM_BYTES);
    mega_kernel<<<444, 256, MEGA_SMEM_BYTES>>>(X, Wq, bq, Wk, bk, Wv, bv);

    vgemv_kernel<<<dim3(8, 4), 256>>>(Wv);
    vcombine_kernel<<<8, 256>>>(bv);

    assemble_kernel<<<SEQ, 256>>>(out);
}

// round 11
// speedup vs baseline: 1.1852x; 1.1217x over previous
#include <cuda_runtime.h>
#include <cstdint>
#include <math.h>

typedef unsigned long long ull;

#define SEQ   2048
#define DM    1024
#define NH    16
#define DH    128
#define HD    2048   // NH*DH

// ---------------- scratch ----------------
__device__ float g_Q[NH * SEQ * DH];   // compacted masked rows, head-major
__device__ float g_K[NH * SEQ * DH];
__device__ float g_V[NH * SEQ * DH];
__device__ float g_xpart[8][DM];
__device__ float g_xmean[DM];
__device__ float g_vpart[4][HD];
__device__ float g_vmean[HD];
__device__ int   g_mask[SEQ];
__device__ int   g_midx[SEQ];
__device__ int   g_kbest[NH * SEQ];
__device__ int   g_mcount;
__device__ int   g_mcount64;

// ---------------- f32x2 helpers ----------------
__device__ __forceinline__ void fma2(ull& d, ull a, ull b) {
    asm("fma.rn.f32x2 %0, %1, %2, %0;" : "+l"(d) : "l"(a), "l"(b));
}
__device__ __forceinline__ ull packf2(float lo, float hi) {
    ull r; asm("mov.b64 %0, {%1, %2};" : "=l"(r) : "f"(lo), "f"(hi)); return r;
}
__device__ __forceinline__ ull add2(ull a, ull b) {
    ull r; asm("add.rn.f32x2 %0, %1, %2;" : "=l"(r) : "l"(a), "l"(b)); return r;
}
__device__ __forceinline__ float f2sum(ull v) {
    float lo, hi; asm("mov.b64 {%0, %1}, %2;" : "=f"(lo), "=f"(hi) : "l"(v));
    return lo + hi;
}
__device__ __forceinline__ void cp16(unsigned dst, const void* src) {
    asm volatile("cp.async.cg.shared.global [%0], [%1], 16;" :: "r"(dst), "l"(src) : "memory");
}
__device__ __forceinline__ void cp_commit() {
    asm volatile("cp.async.commit_group;" ::: "memory");
}
__device__ __forceinline__ void cp_wait0() {
    asm volatile("cp.async.wait_group 0;" ::: "memory");
}

// ---------------- mask decode + compaction ----------------
__global__ void mask_setup_kernel(const unsigned char* __restrict__ p)
{
    __shared__ int sm[SEQ];
    __shared__ int cnt[64];
    __shared__ int base[65];
    __shared__ int not_i32, not_f32;
    int t = threadIdx.x;               // 1024 threads
    if (t == 0) { not_i32 = 0; not_f32 = 0; }
    __syncthreads();
    if (t < 512) {
        unsigned w = ((const unsigned*)p)[t];
        if (!(w == 0u || w == 1u))          atomicExch(&not_i32, 1);
        if (!(w == 0u || w == 0x3F800000u)) atomicExch(&not_f32, 1);
    }
    __syncthreads();
    int cls = (!not_i32) ? 0 : ((!not_f32) ? 1 : 2);
    for (int i = t; i < SEQ; i += 1024) {
        int v;
        if (cls == 0)      v = (((const int*)p)[i]   != 0);
        else if (cls == 1) v = (((const float*)p)[i] != 0.0f);
        else               v = (p[i] != 0);
        sm[i] = v; g_mask[i] = v;
    }
    __syncthreads();
    if (t < 64) {
        int c = 0;
        for (int i = 0; i < 32; i++) c += sm[t * 32 + i];
        cnt[t] = c;
    }
    __syncthreads();
    if (t == 0) {
        int acc = 0;
        for (int c = 0; c < 64; c++) { base[c] = acc; acc += cnt[c]; }
        base[64] = acc;
        g_mcount = acc;
        g_mcount64 = (acc + 63) & ~63;
    }
    __syncthreads();
    if (t < 64) {
        int pos = base[t];
        for (int i = 0; i < 32; i++)
            if (sm[t * 32 + i]) g_midx[pos++] = t * 32 + i;
    }
    __syncthreads();
    int mc = base[64];
    for (int i = t; i < SEQ; i += 1024)
        if (i >= mc) g_midx[i] = 0;
}

// ---------------- pipelined proj: 64(m) x 128(n), k-step 32, 4x4 micro ----------------
// dsm (ull): Xd[64][33] @0 (2112), Wp0[32][66] @2112 (2112), Wp1 @4224 (2112),
//            ridx @6336 (64 int).  bytes = 6336*8 + 256 = 50944
#define PROJ_SMEM_BYTES (6336 * 8 + 256)

__global__ __launch_bounds__(256, 2) void proj_kernel(
    const float* __restrict__ X,
    const float* __restrict__ Wq, const float* __restrict__ bq,
    const float* __restrict__ Wk, const float* __restrict__ bk,
    const float* __restrict__ Wv, const float* __restrict__ bv)
{
    extern __shared__ __align__(16) ull dsm[];
    ull* Xd   = dsm;            // [64][33]
    ull* Wp0  = dsm + 2112;     // [32][66]
    ull* Wp1  = dsm + 4224;     // [32][66]
    int* ridx = (int*)(dsm + 6336);

    const int t  = threadIdx.x;
    const int tx = t & 15, ty = t >> 4;
    const int m0 = blockIdx.y << 6;
    if (m0 >= g_mcount64) return;
    const int n0 = blockIdx.x << 7;

    const float *W, *bias; float* out;
    if (blockIdx.z == 0)      { W = Wq; bias = bq; out = g_Q; }
    else if (blockIdx.z == 1) { W = Wk; bias = bk; out = g_K; }
    else                      { W = Wv; bias = bv; out = g_V; }

    if (t < 64) ridx[t] = g_midx[m0 + t];
    __syncthreads();

    // per-thread X gather rows: r = (t>>5) + 8u, col kk = t&31
    const int kkx = t & 31;
    const int rb  = t >> 5;
    int xrow[8];
    #pragma unroll
    for (int u = 0; u < 8; u++) xrow[u] = ridx[rb + 8 * u];

    // W cp.async chunk geometry: 4 chunks/thread; c = t + 256u; kk = c>>5; c16 = c&31
    const unsigned wb0 = (unsigned)__cvta_generic_to_shared(Wp0);
    const unsigned wb1 = (unsigned)__cvta_generic_to_shared(Wp1);

    // ---- prologue: W(k0=0) -> buf0, X(0) -> regs ----
    #pragma unroll
    for (int u = 0; u < 4; u++) {
        int c = t + 256 * u;
        int kk = c >> 5, c16 = c & 31;
        cp16(wb0 + (unsigned)(kk * 66 + c16 * 2) * 8,
             W + (size_t)kk * HD + n0 + c16 * 4);
    }
    cp_commit();
    float xr[8];
    #pragma unroll
    for (int u = 0; u < 8; u++) xr[u] = X[(size_t)xrow[u] * DM + kkx];
    cp_wait0();
    #pragma unroll
    for (int u = 0; u < 8; u++) Xd[(rb + 8 * u) * 33 + kkx] = packf2(xr[u], xr[u]);
    __syncthreads();

    ull acc[4][4];
    #pragma unroll
    for (int i = 0; i < 4; i++)
        #pragma unroll
        for (int j = 0; j < 4; j++) acc[i][j] = 0ull;

    const int r0 = ty << 2;
    int cur = 0;

    for (int k0 = 0; k0 < DM; k0 += 32) {
        const bool more = (k0 + 32 < DM);
        if (more) {
            unsigned wb = cur ? wb0 : wb1;   // fill alternate buffer
            #pragma unroll
            for (int u = 0; u < 4; u++) {
                int c = t + 256 * u;
                int kk = c >> 5, c16 = c & 31;
                cp16(wb + (unsigned)(kk * 66 + c16 * 2) * 8,
                     W + (size_t)(k0 + 32 + kk) * HD + n0 + c16 * 4);
            }
            cp_commit();
            #pragma unroll
            for (int u = 0; u < 8; u++)
                xr[u] = X[(size_t)xrow[u] * DM + (k0 + 32) + kkx];
        }
        const ull* Wc = cur ? Wp1 : Wp0;
        #pragma unroll 4
        for (int kk = 0; kk < 32; kk++) {
            ull a0 = Xd[(r0 + 0) * 33 + kk];
            ull a1 = Xd[(r0 + 1) * 33 + kk];
            ull a2 = Xd[(r0 + 2) * 33 + kk];
            ull a3 = Xd[(r0 + 3) * 33 + kk];
            const ull* wr = Wc + kk * 66 + tx;
            #pragma unroll
            for (int j = 0; j < 4; j++) {
                ull b = wr[16 * j];
                fma2(acc[0][j], a0, b);
                fma2(acc[1][j], a1, b);
                fma2(acc[2][j], a2, b);
                fma2(acc[3][j], a3, b);
            }
        }
        __syncthreads();            // compute done; Xd reusable, W buf consumed
        if (more) {
            #pragma unroll
            for (int u = 0; u < 8; u++)
                Xd[(rb + 8 * u) * 33 + kkx] = packf2(xr[u], xr[u]);
            cp_wait0();             // alternate W buffer landed
        }
        __syncthreads();
        cur ^= 1;
    }

    const int h = n0 >> 7;                 // n-tile spans exactly one head
    #pragma unroll
    for (int j = 0; j < 4; j++) {
        int cp = tx + 16 * j;
        int d  = 2 * cp;
        ull bpair = *(const ull*)(bias + n0 + d);
        #pragma unroll
        for (int i = 0; i < 4; i++) {
            ull* dst = (ull*)(out + (size_t)(h * SEQ + m0 + r0 + i) * DH + d);
            *dst = add2(acc[i][j], bpair);
        }
    }
}

// ---------------- score kernel: 64q x 64k tiles, register argmin + shfl ----------------
// sm floats: Qs[64][128] @0 (8192), Ks[64][130] @8192 (8320) -> 16512 floats
#define SC_SMEM_BYTES (16512 * 4)

__global__ __launch_bounds__(256, 2) void score_kernel(void)
{
    extern __shared__ __align__(16) float sm[];
    float* Qs = sm;            // stride 128 (a-loads are broadcast)
    float* Ks = sm + 8192;     // stride 130 (b-loads conflict-free)

    const int t  = threadIdx.x;
    const int tx = t & 15, ty = t >> 4;
    const int h  = blockIdx.y;
    const int q0 = blockIdx.x << 6;
    const int mc = g_mcount;
    if (q0 >= mc) return;

    const float* Qg = g_Q + (size_t)(h * SEQ + q0) * DH;
    #pragma unroll
    for (int u = 0; u < 8; u++) {
        int i = t + u * 256;
        float4 v = ((const float4*)Qg)[i];
        int r = i >> 5, dd = (i & 31) << 2;
        ull* p = (ull*)&Qs[r * 128 + dd];
        p[0] = packf2(v.x, v.y); p[1] = packf2(v.z, v.w);
    }

    float bv_[4]; int bi_[4];
    #pragma unroll
    for (int i = 0; i < 4; i++) { bv_[i] = INFINITY; bi_[i] = 0; }

    const int r0 = ty << 2;
    const int nkt = g_mcount64 >> 6;
    for (int kt = 0; kt < nkt; kt++) {
        const int k0 = kt << 6;
        __syncthreads();               // Q fill / prior reads done
        const float* Kg = g_K + (size_t)(h * SEQ + k0) * DH;
        #pragma unroll
        for (int u = 0; u < 8; u++) {
            int i = t + u * 256;
            float4 v = ((const float4*)Kg)[i];
            int r = i >> 5, dd = (i & 31) << 2;
            ull* p = (ull*)&Ks[r * 130 + dd];
            p[0] = packf2(v.x, v.y); p[1] = packf2(v.z, v.w);
        }
        __syncthreads();

        ull acc[4][4];
        #pragma unroll
        for (int i = 0; i < 4; i++)
            #pragma unroll
            for (int j = 0; j < 4; j++) acc[i][j] = 0ull;

        #pragma unroll 4
        for (int dp = 0; dp < 64; dp++) {
            ull a0 = *(const ull*)&Qs[(r0 + 0) * 128 + 2 * dp];
            ull a1 = *(const ull*)&Qs[(r0 + 1) * 128 + 2 * dp];
            ull a2 = *(const ull*)&Qs[(r0 + 2) * 128 + 2 * dp];
            ull a3 = *(const ull*)&Qs[(r0 + 3) * 128 + 2 * dp];
            #pragma unroll
            for (int j = 0; j < 4; j++) {
                ull b = *(const ull*)&Ks[(tx + 16 * j) * 130 + 2 * dp];
                fma2(acc[0][j], a0, b);
                fma2(acc[1][j], a1, b);
                fma2(acc[2][j], a2, b);
                fma2(acc[3][j], a3, b);
            }
        }
        #pragma unroll
        for (int i = 0; i < 4; i++) {
            #pragma unroll
            for (int j = 0; j < 4; j++) {
                int c = k0 + tx + 16 * j;
                float s = f2sum(acc[i][j]);
                if (c < mc && s < bv_[i]) { bv_[i] = s; bi_[i] = c; }
            }
        }
    }
    // half-warp shuffle argmin (row r0+i owned by 16 lanes with same ty)
    #pragma unroll
    for (int i = 0; i < 4; i++) {
        #pragma unroll
        for (int off = 8; off >= 1; off >>= 1) {
            float ov = __shfl_xor_sync(0xffffffffu, bv_[i], off);
            int   oi = __shfl_xor_sync(0xffffffffu, bi_[i], off);
            if (ov < bv_[i]) { bv_[i] = ov; bi_[i] = oi; }
        }
    }
    if (tx == 0) {
        #pragma unroll
        for (int i = 0; i < 4; i++) {
            int row = q0 + r0 + i;
            if (row < mc) g_kbest[h * SEQ + g_midx[row]] = bi_[i];
        }
    }
}

// ---------------- mean(X) and mean-V via linearity ----------------
__global__ void xpart_kernel(const float* __restrict__ X)
{
    int j  = blockIdx.x * 256 + threadIdx.x;   // grid.x = 4
    int rb = blockIdx.y;                        // 8
    const float* p = X + (size_t)rb * 256 * DM + j;
    float s = 0.0f;
    #pragma unroll 8
    for (int r = 0; r < 256; r++) s += p[(size_t)r * DM];
    g_xpart[rb][j] = s;
}
__global__ void xmean_kernel(void)
{
    int j = blockIdx.x * 256 + threadIdx.x;    // grid 4
    float s = 0.0f;
    #pragma unroll
    for (int rb = 0; rb < 8; rb++) s += g_xpart[rb][j];
    g_xmean[j] = s * (1.0f / 2048.0f);
}
__global__ void vgemv_kernel(const float* __restrict__ Wv)
{
    __shared__ float xm[256];
    int t = threadIdx.x;
    int part = blockIdx.y;                     // 4 k-slices of 256
    xm[t] = g_xmean[part * 256 + t];
    __syncthreads();
    int c = blockIdx.x * 256 + t;              // grid.x 8
    float a0 = 0, a1 = 0, a2 = 0, a3 = 0;
    const float* Wp = Wv + (size_t)part * 256 * HD + c;
    for (int j = 0; j < 256; j += 4) {
        a0 += xm[j + 0] * Wp[(size_t)(j + 0) * HD];
        a1 += xm[j + 1] * Wp[(size_t)(j + 1) * HD];
        a2 += xm[j + 2] * Wp[(size_t)(j + 2) * HD];
        a3 += xm[j + 3] * Wp[(size_t)(j + 3) * HD];
    }
    g_vpart[part][c] = (a0 + a1) + (a2 + a3);
}
__global__ void vcombine_kernel(const float* __restrict__ bv)
{
    int c = blockIdx.x * 256 + threadIdx.x;    // grid 8
    g_vmean[c] = ((g_vpart[0][c] + g_vpart[1][c]) + (g_vpart[2][c] + g_vpart[3][c])) + bv[c];
}

// ---------------- output assembly ----------------
__global__ void assemble_kernel(float* __restrict__ out)
{
    int s = blockIdx.x;
    int t = threadIdx.x;               // 256
    if (g_mask[s]) {
        #pragma unroll
        for (int i = 0; i < 8; i++) {
            int idx = i * 256 + t;
            int h = idx >> 7, d = idx & 127;
            int kb = g_kbest[h * SEQ + s];
            out[(size_t)s * HD + idx] = g_V[(size_t)(h * SEQ + kb) * DH + d];
        }
    } else {
        #pragma unroll
        for (int i = 0; i < 8; i++) {
            int idx = i * 256 + t;
            out[(size_t)s * HD + idx] = g_vmean[idx];
        }
    }
}

// ---------------- launch ----------------
extern "C" void kernel_launch(void* const* d_in, const int* in_sizes, int n_in,
                              void* d_out, int out_size)
{
    const float* X          = (const float*)d_in[0];
    const unsigned char* mp = (const unsigned char*)d_in[1];
    const float* Wq = (const float*)d_in[2];
    const float* bq = (const float*)d_in[3];
    const float* Wk = (const float*)d_in[4];
    const float* bk = (const float*)d_in[5];
    const float* Wv = (const float*)d_in[6];
    const float* bv = (const float*)d_in[7];
    float* out = (float*)d_out;

    mask_setup_kernel<<<1, 1024>>>(mp);

    xpart_kernel<<<dim3(4, 8), 256>>>(X);
    xmean_kernel<<<4, 256>>>();

    cudaFuncSetAttribute(proj_kernel, cudaFuncAttributeMaxDynamicSharedMemorySize, PROJ_SMEM_BYTES);
    proj_kernel<<<dim3(HD / 128, SEQ / 64, 3), 256, PROJ_SMEM_BYTES>>>(X, Wq, bq, Wk, bk, Wv, bv);

    vgemv_kernel<<<dim3(8, 4), 256>>>(Wv);
    vcombine_kernel<<<8, 256>>>(bv);

    cudaFuncSetAttribute(score_kernel, cudaFuncAttributeMaxDynamicSharedMemorySize, SC_SMEM_BYTES);
    score_kernel<<<dim3(SEQ / 64, NH), 256, SC_SMEM_BYTES>>>();

    assemble_kernel<<<SEQ, 256>>>(out);
}